// round 3
// baseline (speedup 1.0000x reference)
#include <cuda_runtime.h>
#include <math.h>

#define BTOT 8192      // B*T rows
#define CDIM 2048      // channels
#define TSEQ 2048      // sequence length
#define NHEAD 16
#define HDIM 128

// -------- scratch (device globals; allocation-free) --------
__device__ float g_nx [BTOT * CDIM];
__device__ float g_q  [BTOT * CDIM];
__device__ float g_k  [BTOT * CDIM];
__device__ float g_v  [BTOT * CDIM];
__device__ float g_att[BTOT * CDIM];

// ===================== LayerNorm =====================
__global__ __launch_bounds__(256) void ln_kernel(const float* __restrict__ x,
                                                 const float* __restrict__ gamma,
                                                 const float* __restrict__ beta) {
    int row = blockIdx.x;
    int tid = threadIdx.x;
    const float* px = x + row * CDIM;

    float4 a0 = *(const float4*)(px + tid * 4);
    float4 a1 = *(const float4*)(px + 1024 + tid * 4);

    float s = a0.x + a0.y + a0.z + a0.w + a1.x + a1.y + a1.z + a1.w;
    float q = a0.x*a0.x + a0.y*a0.y + a0.z*a0.z + a0.w*a0.w
            + a1.x*a1.x + a1.y*a1.y + a1.z*a1.z + a1.w*a1.w;

    #pragma unroll
    for (int off = 16; off; off >>= 1) {
        s += __shfl_xor_sync(0xffffffffu, s, off);
        q += __shfl_xor_sync(0xffffffffu, q, off);
    }
    __shared__ float sh[16];
    if ((tid & 31) == 0) { sh[tid >> 5] = s; sh[8 + (tid >> 5)] = q; }
    __syncthreads();
    float ts = 0.f, tq = 0.f;
    #pragma unroll
    for (int i = 0; i < 8; i++) { ts += sh[i]; tq += sh[8 + i]; }

    float mu   = ts * (1.f / 2048.f);
    float var  = tq * (1.f / 2048.f) - mu * mu;
    float rstd = rsqrtf(var + 1e-5f);

    float4 g0 = *(const float4*)(gamma + tid * 4);
    float4 g1 = *(const float4*)(gamma + 1024 + tid * 4);
    float4 b0 = *(const float4*)(beta + tid * 4);
    float4 b1 = *(const float4*)(beta + 1024 + tid * 4);

    float* po = g_nx + row * CDIM;
    float4 o0, o1;
    o0.x = (a0.x - mu) * rstd * g0.x + b0.x;
    o0.y = (a0.y - mu) * rstd * g0.y + b0.y;
    o0.z = (a0.z - mu) * rstd * g0.z + b0.z;
    o0.w = (a0.w - mu) * rstd * g0.w + b0.w;
    o1.x = (a1.x - mu) * rstd * g1.x + b1.x;
    o1.y = (a1.y - mu) * rstd * g1.y + b1.y;
    o1.z = (a1.z - mu) * rstd * g1.z + b1.z;
    o1.w = (a1.w - mu) * rstd * g1.w + b1.w;
    *(float4*)(po + tid * 4)        = o0;
    *(float4*)(po + 1024 + tid * 4) = o1;
}

// ===================== SGEMM: Y = A[M,K] * W[K,N] + bias (+ residual) =====================
// 128x128 block tile, BK=8, 256 threads, 8x8 per-thread microtile.
template<int MODE>   // 0: +bias ; 1: +bias + residual
__global__ __launch_bounds__(256) void sgemm_kernel(const float* __restrict__ A,
                                                    const float* __restrict__ W,
                                                    const float* __restrict__ bias,
                                                    const float* __restrict__ R,
                                                    float* __restrict__ Y,
                                                    int M, int N, int K) {
    __shared__ float As[8][128];
    __shared__ float Bs[8][128];

    int tid = threadIdx.x;
    int tx = tid & 15, ty = tid >> 4;
    int bm = blockIdx.y * 128, bn = blockIdx.x * 128;

    int arow = tid >> 1;            // 0..127
    int acol = (tid & 1) * 4;       // 0 or 4
    int brow = tid >> 5;            // 0..7
    int bcol = (tid & 31) * 4;      // 0..124

    const float* Aptr = A + (bm + arow) * K + acol;
    const float* Bptr = W + brow * N + bn + bcol;

    float acc[8][8];
    #pragma unroll
    for (int i = 0; i < 8; i++)
        #pragma unroll
        for (int j = 0; j < 8; j++) acc[i][j] = 0.f;

    float4 aReg = *(const float4*)(Aptr);
    float4 bReg = *(const float4*)(Bptr);

    for (int k0 = 0; k0 < K; k0 += 8) {
        As[acol + 0][arow] = aReg.x;
        As[acol + 1][arow] = aReg.y;
        As[acol + 2][arow] = aReg.z;
        As[acol + 3][arow] = aReg.w;
        *(float4*)&Bs[brow][bcol] = bReg;
        __syncthreads();

        if (k0 + 8 < K) {  // prefetch next tile
            aReg = *(const float4*)(Aptr + k0 + 8);
            bReg = *(const float4*)(Bptr + (size_t)(k0 + 8) * N);
        }

        #pragma unroll
        for (int k = 0; k < 8; k++) {
            float ar[8], br[8];
            *(float4*)(ar)     = *(const float4*)&As[k][ty * 8];
            *(float4*)(ar + 4) = *(const float4*)&As[k][ty * 8 + 4];
            *(float4*)(br)     = *(const float4*)&Bs[k][tx * 8];
            *(float4*)(br + 4) = *(const float4*)&Bs[k][tx * 8 + 4];
            #pragma unroll
            for (int i = 0; i < 8; i++)
                #pragma unroll
                for (int j = 0; j < 8; j++)
                    acc[i][j] += ar[i] * br[j];
        }
        __syncthreads();
    }

    #pragma unroll
    for (int i = 0; i < 8; i++) {
        int row = bm + ty * 8 + i;
        #pragma unroll
        for (int j = 0; j < 8; j += 4) {
            int col = bn + tx * 8 + j;
            float4 o;
            o.x = acc[i][j + 0] + bias[col + 0];
            o.y = acc[i][j + 1] + bias[col + 1];
            o.z = acc[i][j + 2] + bias[col + 2];
            o.w = acc[i][j + 3] + bias[col + 3];
            if (MODE == 1) {
                const float4 r = *(const float4*)(R + (size_t)row * N + col);
                o.x += r.x; o.y += r.y; o.z += r.z; o.w += r.w;
            }
            *(float4*)(Y + (size_t)row * N + col) = o;
        }
    }
}

// ===================== RoPE (in-place on g_q / g_k) =====================
__global__ __launch_bounds__(256) void rope_kernel() {
    int row = blockIdx.x;                  // 0..BTOT-1
    float* buf = (blockIdx.y == 0) ? g_q : g_k;
    int t = row & (TSEQ - 1);              // t = row % T

    __shared__ float cs[64], sn[64];
    if (threadIdx.x < 64) {
        float inv = powf(10000.f, -(float)threadIdx.x / 64.f);
        float ang = (float)t * inv;
        cs[threadIdx.x] = cosf(ang);
        sn[threadIdx.x] = sinf(ang);
    }
    __syncthreads();

    float* p = buf + (size_t)row * CDIM;
    for (int idx = threadIdx.x; idx < NHEAD * 64; idx += 256) {
        int h = idx >> 6, f = idx & 63;
        float a = p[h * 128 + f];
        float b = p[h * 128 + 64 + f];
        p[h * 128 + f]      = a * cs[f] - b * sn[f];
        p[h * 128 + 64 + f] = b * cs[f] + a * sn[f];
    }
}

// ===================== Flash attention (fp32, causal) =====================
// grid: (T/64, H, B); block: 256 threads (ty=tid/16 in 0..15, tx=tid%16)
// smem: Qt[128][64], Kt[128][64] (transposed for conflict-free S), Vs[64][128], Ps[64][65]
#define FLASH_SMEM ((128*64*2 + 64*128 + 64*65) * 4)

__global__ __launch_bounds__(256) void flash_kernel() {
    extern __shared__ float sm[];
    float* Qt = sm;                 // [128][64]
    float* Kt = Qt + 128 * 64;      // [128][64]
    float* Vs = Kt + 128 * 64;      // [64][128]
    float* Ps = Vs + 64 * 128;      // [64][65]

    int qb = blockIdx.x, h = blockIdx.y, b = blockIdx.z;
    int tid = threadIdx.x;
    int tx = tid & 15, ty = tid >> 4;

    int base = (b * TSEQ) * CDIM + h * HDIM;   // max ~16.7M, fits int

    // Load Q block transposed: Qt[d][r]
    #pragma unroll
    for (int it = 0; it < 8; it++) {
        int f4 = tid + it * 256;          // 0..2047
        int r  = f4 >> 5;                 // 0..63
        int d4 = (f4 & 31) * 4;
        float4 v = *(const float4*)(g_q + base + (qb * 64 + r) * CDIM + d4);
        Qt[(d4 + 0) * 64 + r] = v.x;
        Qt[(d4 + 1) * 64 + r] = v.y;
        Qt[(d4 + 2) * 64 + r] = v.z;
        Qt[(d4 + 3) * 64 + r] = v.w;
    }

    float m_i[4], l_i[4], O[4][8];
    #pragma unroll
    for (int i = 0; i < 4; i++) {
        m_i[i] = -1e30f; l_i[i] = 0.f;
        #pragma unroll
        for (int j = 0; j < 8; j++) O[i][j] = 0.f;
    }

    const float scale = 0.08838834764831845f;  // 1/sqrt(128)
    int nkb = qb + 1;

    for (int kb = 0; kb < nkb; kb++) {
        __syncthreads();   // prev PV done (and Q load visible on first iter)

        // Load K (transposed) and V tiles
        #pragma unroll
        for (int it = 0; it < 8; it++) {
            int f4 = tid + it * 256;
            int r  = f4 >> 5;
            int d4 = (f4 & 31) * 4;
            int grow = base + (kb * 64 + r) * CDIM + d4;
            float4 kv = *(const float4*)(g_k + grow);
            Kt[(d4 + 0) * 64 + r] = kv.x;
            Kt[(d4 + 1) * 64 + r] = kv.y;
            Kt[(d4 + 2) * 64 + r] = kv.z;
            Kt[(d4 + 3) * 64 + r] = kv.w;
            *(float4*)&Vs[r * 128 + d4] = *(const float4*)(g_v + grow);
        }
        __syncthreads();

        // S = Q K^T  (each thread: 4x4 tile)
        float s[4][4];
        #pragma unroll
        for (int i = 0; i < 4; i++)
            #pragma unroll
            for (int j = 0; j < 4; j++) s[i][j] = 0.f;

        #pragma unroll 8
        for (int d = 0; d < 128; d++) {
            float4 qv = *(const float4*)(Qt + d * 64 + (ty << 2));
            float4 kv = *(const float4*)(Kt + d * 64 + (tx << 2));
            s[0][0] += qv.x * kv.x; s[0][1] += qv.x * kv.y; s[0][2] += qv.x * kv.z; s[0][3] += qv.x * kv.w;
            s[1][0] += qv.y * kv.x; s[1][1] += qv.y * kv.y; s[1][2] += qv.y * kv.z; s[1][3] += qv.y * kv.w;
            s[2][0] += qv.z * kv.x; s[2][1] += qv.z * kv.y; s[2][2] += qv.z * kv.z; s[2][3] += qv.z * kv.w;
            s[3][0] += qv.w * kv.x; s[3][1] += qv.w * kv.y; s[3][2] += qv.w * kv.z; s[3][3] += qv.w * kv.w;
        }

        // mask + online softmax (row groups of 16 lanes share a row)
        #pragma unroll
        for (int i = 0; i < 4; i++) {
            int gq = qb * 64 + ty * 4 + i;
            float mx = -1e30f;
            #pragma unroll
            for (int j = 0; j < 4; j++) {
                int gk = kb * 64 + tx * 4 + j;
                float v = (gk <= gq) ? s[i][j] * scale : -1e9f;
                s[i][j] = v;
                mx = fmaxf(mx, v);
            }
            #pragma unroll
            for (int off = 8; off; off >>= 1)
                mx = fmaxf(mx, __shfl_xor_sync(0xffffffffu, mx, off));
            float mnew  = fmaxf(m_i[i], mx);
            float alpha = __expf(m_i[i] - mnew);
            float rs = 0.f;
            #pragma unroll
            for (int j = 0; j < 4; j++) {
                float p = __expf(s[i][j] - mnew);
                Ps[(ty * 4 + i) * 65 + tx * 4 + j] = p;
                rs += p;
            }
            #pragma unroll
            for (int off = 8; off; off >>= 1)
                rs += __shfl_xor_sync(0xffffffffu, rs, off);
            l_i[i] = l_i[i] * alpha + rs;
            m_i[i] = mnew;
            #pragma unroll
            for (int j = 0; j < 8; j++) O[i][j] *= alpha;
        }
        __syncthreads();

        // O += P * V   (each thread: 4 rows x 8 cols)
        #pragma unroll 4
        for (int kk = 0; kk < 64; kk++) {
            float p0 = Ps[(ty * 4 + 0) * 65 + kk];
            float p1 = Ps[(ty * 4 + 1) * 65 + kk];
            float p2 = Ps[(ty * 4 + 2) * 65 + kk];
            float p3 = Ps[(ty * 4 + 3) * 65 + kk];
            float4 va = *(const float4*)(Vs + kk * 128 + (tx << 3));
            float4 vb = *(const float4*)(Vs + kk * 128 + (tx << 3) + 4);
            O[0][0] += p0 * va.x; O[0][1] += p0 * va.y; O[0][2] += p0 * va.z; O[0][3] += p0 * va.w;
            O[0][4] += p0 * vb.x; O[0][5] += p0 * vb.y; O[0][6] += p0 * vb.z; O[0][7] += p0 * vb.w;
            O[1][0] += p1 * va.x; O[1][1] += p1 * va.y; O[1][2] += p1 * va.z; O[1][3] += p1 * va.w;
            O[1][4] += p1 * vb.x; O[1][5] += p1 * vb.y; O[1][6] += p1 * vb.z; O[1][7] += p1 * vb.w;
            O[2][0] += p2 * va.x; O[2][1] += p2 * va.y; O[2][2] += p2 * va.z; O[2][3] += p2 * va.w;
            O[2][4] += p2 * vb.x; O[2][5] += p2 * vb.y; O[2][6] += p2 * vb.z; O[2][7] += p2 * vb.w;
            O[3][0] += p3 * va.x; O[3][1] += p3 * va.y; O[3][2] += p3 * va.z; O[3][3] += p3 * va.w;
            O[3][4] += p3 * vb.x; O[3][5] += p3 * vb.y; O[3][6] += p3 * vb.z; O[3][7] += p3 * vb.w;
        }
    }

    // epilogue: normalize, store
    #pragma unroll
    for (int i = 0; i < 4; i++) {
        float inv = 1.f / l_i[i];
        int r = qb * 64 + ty * 4 + i;
        float* po = g_att + base + r * CDIM + (tx << 3);
        float4 w0 = make_float4(O[i][0] * inv, O[i][1] * inv, O[i][2] * inv, O[i][3] * inv);
        float4 w1 = make_float4(O[i][4] * inv, O[i][5] * inv, O[i][6] * inv, O[i][7] * inv);
        *(float4*)(po)     = w0;
        *(float4*)(po + 4) = w1;
    }
}

// ===================== launch =====================
extern "C" void kernel_launch(void* const* d_in, const int* in_sizes, int n_in,
                              void* d_out, int out_size) {
    const float* x    = (const float*)d_in[0];
    const float* ln_g = (const float*)d_in[1];
    const float* ln_b = (const float*)d_in[2];
    const float* Wq   = (const float*)d_in[3];
    const float* bq   = (const float*)d_in[4];
    const float* Wk   = (const float*)d_in[5];
    const float* bk   = (const float*)d_in[6];
    const float* Wv   = (const float*)d_in[7];
    const float* bv   = (const float*)d_in[8];
    const float* Wo   = (const float*)d_in[9];
    const float* bo   = (const float*)d_in[10];
    float* out = (float*)d_out;

    float *nx, *qp, *kp, *vp, *ap;
    cudaGetSymbolAddress((void**)&nx, g_nx);
    cudaGetSymbolAddress((void**)&qp, g_q);
    cudaGetSymbolAddress((void**)&kp, g_k);
    cudaGetSymbolAddress((void**)&vp, g_v);
    cudaGetSymbolAddress((void**)&ap, g_att);

    // persists process-wide after the correctness run; safe to repeat
    cudaFuncSetAttribute(flash_kernel, cudaFuncAttributeMaxDynamicSharedMemorySize, FLASH_SMEM);

    ln_kernel<<<BTOT, 256>>>(x, ln_g, ln_b);

    dim3 gg(CDIM / 128, BTOT / 128);
    sgemm_kernel<0><<<gg, 256>>>(nx, Wq, bq, nullptr, qp, BTOT, CDIM, CDIM);
    sgemm_kernel<0><<<gg, 256>>>(nx, Wk, bk, nullptr, kp, BTOT, CDIM, CDIM);
    sgemm_kernel<0><<<gg, 256>>>(nx, Wv, bv, nullptr, vp, BTOT, CDIM, CDIM);

    rope_kernel<<<dim3(BTOT, 2), 256>>>();

    flash_kernel<<<dim3(TSEQ / 64, NHEAD, 4), 256, FLASH_SMEM>>>();

    sgemm_kernel<1><<<gg, 256>>>(ap, Wo, bo, x, out, BTOT, CDIM, CDIM);
}

// round 4
// speedup vs baseline: 1.7860x; 1.7860x over previous
#include <cuda_runtime.h>
#include <math.h>
#include <stdint.h>

#define BTOT 8192      // B*T rows
#define CDIM 2048      // channels
#define TSEQ 2048      // sequence length
#define NHEAD 16
#define HDIM 128

// -------- scratch (device globals; allocation-free) --------
__device__ float g_nx [BTOT * CDIM];
__device__ float g_q  [BTOT * CDIM];
__device__ float g_k  [BTOT * CDIM];
__device__ float g_v  [BTOT * CDIM];
__device__ float g_att[BTOT * CDIM];

// ===================== LayerNorm =====================
__global__ __launch_bounds__(256) void ln_kernel(const float* __restrict__ x,
                                                 const float* __restrict__ gamma,
                                                 const float* __restrict__ beta) {
    int row = blockIdx.x;
    int tid = threadIdx.x;
    const float* px = x + row * CDIM;

    float4 a0 = *(const float4*)(px + tid * 4);
    float4 a1 = *(const float4*)(px + 1024 + tid * 4);

    float s = a0.x + a0.y + a0.z + a0.w + a1.x + a1.y + a1.z + a1.w;
    float q = a0.x*a0.x + a0.y*a0.y + a0.z*a0.z + a0.w*a0.w
            + a1.x*a1.x + a1.y*a1.y + a1.z*a1.z + a1.w*a1.w;

    #pragma unroll
    for (int off = 16; off; off >>= 1) {
        s += __shfl_xor_sync(0xffffffffu, s, off);
        q += __shfl_xor_sync(0xffffffffu, q, off);
    }
    __shared__ float sh[16];
    if ((tid & 31) == 0) { sh[tid >> 5] = s; sh[8 + (tid >> 5)] = q; }
    __syncthreads();
    float ts = 0.f, tq = 0.f;
    #pragma unroll
    for (int i = 0; i < 8; i++) { ts += sh[i]; tq += sh[8 + i]; }

    float mu   = ts * (1.f / 2048.f);
    float var  = tq * (1.f / 2048.f) - mu * mu;
    float rstd = rsqrtf(var + 1e-5f);

    float4 g0 = *(const float4*)(gamma + tid * 4);
    float4 g1 = *(const float4*)(gamma + 1024 + tid * 4);
    float4 b0 = *(const float4*)(beta + tid * 4);
    float4 b1 = *(const float4*)(beta + 1024 + tid * 4);

    float* po = g_nx + row * CDIM;
    float4 o0, o1;
    o0.x = (a0.x - mu) * rstd * g0.x + b0.x;
    o0.y = (a0.y - mu) * rstd * g0.y + b0.y;
    o0.z = (a0.z - mu) * rstd * g0.z + b0.z;
    o0.w = (a0.w - mu) * rstd * g0.w + b0.w;
    o1.x = (a1.x - mu) * rstd * g1.x + b1.x;
    o1.y = (a1.y - mu) * rstd * g1.y + b1.y;
    o1.z = (a1.z - mu) * rstd * g1.z + b1.z;
    o1.w = (a1.w - mu) * rstd * g1.w + b1.w;
    *(float4*)(po + tid * 4)        = o0;
    *(float4*)(po + 1024 + tid * 4) = o1;
}

// ===================== tf32 tensor-core GEMM =====================
// Y = A[M,K] * W[K,N] + bias (+ residual).  A, W row-major.
// 128x128 block tile, BK=32, 256 threads (8 warps, 2x4), warp tile 64x32,
// mma.sync.m16n8k8 tf32. Inputs rounded to tf32 via cvt.rna at smem store.

__device__ __forceinline__ float to_tf32(float x) {
    uint32_t u;
    asm("cvt.rna.tf32.f32 %0, %1;" : "=r"(u) : "f"(x));
    return __uint_as_float(u);
}

template<int MODE>   // 0: +bias ; 1: +bias + residual
__global__ __launch_bounds__(256) void tgemm_kernel(const float* __restrict__ A,
                                                    const float* __restrict__ W,
                                                    const float* __restrict__ bias,
                                                    const float* __restrict__ R,
                                                    float* __restrict__ Y,
                                                    int M, int N, int K) {
    __shared__ float As[128][36];   // [m][k], pad -> bank = (4m+k)%32, conflict-free frags
    __shared__ float Bs[32][136];   // [k][n], pad -> bank = (8k+n)%32, conflict-free frags

    int tid  = threadIdx.x;
    int lane = tid & 31, warp = tid >> 5;
    int wm = warp >> 2;             // 0..1  -> 64 rows
    int wn = warp & 3;              // 0..3  -> 32 cols
    int bm = blockIdx.y * 128, bn = blockIdx.x * 128;

    int ldr = tid >> 3;             // 0..31 : A row / B (k) row
    int ldc = (tid & 7) * 4;        // 0..28 : col within 32-wide chunk

    const float* Ap = A + (size_t)(bm + ldr) * K + ldc;
    const float* Bp = W + (size_t)ldr * N + bn + ldc;

    float4 aR[4], bR[4];
    #pragma unroll
    for (int it = 0; it < 4; it++) {
        aR[it] = *(const float4*)(Ap + (size_t)(it * 32) * K);   // rows ldr+32*it, k 0..31
        bR[it] = *(const float4*)(Bp + it * 32);                 // k=ldr, cols chunked
    }

    float c[4][4][4];
    #pragma unroll
    for (int mi = 0; mi < 4; mi++)
        #pragma unroll
        for (int ni = 0; ni < 4; ni++)
            #pragma unroll
            for (int r = 0; r < 4; r++) c[mi][ni][r] = 0.f;

    int mbase = wm * 64;
    int nbase = wn * 32;
    int lq = lane >> 2;   // 0..7
    int lr = lane & 3;    // 0..3

    for (int k0 = 0; k0 < K; k0 += 32) {
        // stage to smem (with tf32 rounding)
        #pragma unroll
        for (int it = 0; it < 4; it++) {
            float4 av = aR[it];
            float4 sa = make_float4(to_tf32(av.x), to_tf32(av.y), to_tf32(av.z), to_tf32(av.w));
            *(float4*)&As[ldr + it * 32][ldc] = sa;
            float4 bv = bR[it];
            float4 sb = make_float4(to_tf32(bv.x), to_tf32(bv.y), to_tf32(bv.z), to_tf32(bv.w));
            *(float4*)&Bs[ldr][ldc + it * 32] = sb;
        }
        __syncthreads();

        if (k0 + 32 < K) {   // prefetch next tile
            #pragma unroll
            for (int it = 0; it < 4; it++) {
                aR[it] = *(const float4*)(Ap + (size_t)(it * 32) * K + (k0 + 32));
                bR[it] = *(const float4*)(Bp + (size_t)(k0 + 32) * N + it * 32);
            }
        }

        #pragma unroll
        for (int kc = 0; kc < 4; kc++) {
            int kk = kc * 8;
            uint32_t a[4][4], b[4][2];
            #pragma unroll
            for (int mi = 0; mi < 4; mi++) {
                int r0 = mbase + mi * 16 + lq;
                int cc = kk + lr;
                a[mi][0] = __float_as_uint(As[r0    ][cc    ]);
                a[mi][1] = __float_as_uint(As[r0 + 8][cc    ]);
                a[mi][2] = __float_as_uint(As[r0    ][cc + 4]);
                a[mi][3] = __float_as_uint(As[r0 + 8][cc + 4]);
            }
            #pragma unroll
            for (int ni = 0; ni < 4; ni++) {
                int rr = kk + lr;
                int nc = nbase + ni * 8 + lq;
                b[ni][0] = __float_as_uint(Bs[rr    ][nc]);
                b[ni][1] = __float_as_uint(Bs[rr + 4][nc]);
            }
            #pragma unroll
            for (int mi = 0; mi < 4; mi++)
                #pragma unroll
                for (int ni = 0; ni < 4; ni++)
                    asm volatile(
                        "mma.sync.aligned.m16n8k8.row.col.f32.tf32.tf32.f32 "
                        "{%0,%1,%2,%3}, {%4,%5,%6,%7}, {%8,%9}, {%0,%1,%2,%3};"
                        : "+f"(c[mi][ni][0]), "+f"(c[mi][ni][1]),
                          "+f"(c[mi][ni][2]), "+f"(c[mi][ni][3])
                        : "r"(a[mi][0]), "r"(a[mi][1]), "r"(a[mi][2]), "r"(a[mi][3]),
                          "r"(b[ni][0]), "r"(b[ni][1]));
        }
        __syncthreads();
    }

    // epilogue: bias (+residual), write fp32
    #pragma unroll
    for (int mi = 0; mi < 4; mi++) {
        int r0 = bm + mbase + mi * 16 + lq;
        #pragma unroll
        for (int ni = 0; ni < 4; ni++) {
            int cb = bn + nbase + ni * 8 + 2 * lr;
            float bx = bias[cb], by = bias[cb + 1];
            float2 v0 = make_float2(c[mi][ni][0] + bx, c[mi][ni][1] + by);
            float2 v1 = make_float2(c[mi][ni][2] + bx, c[mi][ni][3] + by);
            if (MODE == 1) {
                float2 r0v = *(const float2*)(R + (size_t)r0 * N + cb);
                float2 r1v = *(const float2*)(R + (size_t)(r0 + 8) * N + cb);
                v0.x += r0v.x; v0.y += r0v.y;
                v1.x += r1v.x; v1.y += r1v.y;
            }
            *(float2*)(Y + (size_t)r0 * N + cb)       = v0;
            *(float2*)(Y + (size_t)(r0 + 8) * N + cb) = v1;
        }
    }
}

// ===================== RoPE (in-place on g_q / g_k) =====================
__global__ __launch_bounds__(256) void rope_kernel() {
    int row = blockIdx.x;                  // 0..BTOT-1
    float* buf = (blockIdx.y == 0) ? g_q : g_k;
    int t = row & (TSEQ - 1);              // t = row % T

    __shared__ float cs[64], sn[64];
    if (threadIdx.x < 64) {
        float inv = powf(10000.f, -(float)threadIdx.x / 64.f);
        float ang = (float)t * inv;
        cs[threadIdx.x] = cosf(ang);
        sn[threadIdx.x] = sinf(ang);
    }
    __syncthreads();

    float* p = buf + (size_t)row * CDIM;
    for (int idx = threadIdx.x; idx < NHEAD * 64; idx += 256) {
        int h = idx >> 6, f = idx & 63;
        float a = p[h * 128 + f];
        float b = p[h * 128 + 64 + f];
        p[h * 128 + f]      = a * cs[f] - b * sn[f];
        p[h * 128 + 64 + f] = b * cs[f] + a * sn[f];
    }
}

// ===================== Flash attention (fp32, causal) =====================
// grid: (T/64, H, B); block: 256 threads (ty=tid/16 in 0..15, tx=tid%16)
#define FLASH_SMEM ((128*64*2 + 64*128 + 64*65) * 4)

__global__ __launch_bounds__(256) void flash_kernel() {
    extern __shared__ float sm[];
    float* Qt = sm;                 // [128][64]
    float* Kt = Qt + 128 * 64;      // [128][64]
    float* Vs = Kt + 128 * 64;      // [64][128]
    float* Ps = Vs + 64 * 128;      // [64][65]

    int qb = blockIdx.x, h = blockIdx.y, b = blockIdx.z;
    int tid = threadIdx.x;
    int tx = tid & 15, ty = tid >> 4;

    int base = (b * TSEQ) * CDIM + h * HDIM;

    #pragma unroll
    for (int it = 0; it < 8; it++) {
        int f4 = tid + it * 256;
        int r  = f4 >> 5;
        int d4 = (f4 & 31) * 4;
        float4 v = *(const float4*)(g_q + base + (qb * 64 + r) * CDIM + d4);
        Qt[(d4 + 0) * 64 + r] = v.x;
        Qt[(d4 + 1) * 64 + r] = v.y;
        Qt[(d4 + 2) * 64 + r] = v.z;
        Qt[(d4 + 3) * 64 + r] = v.w;
    }

    float m_i[4], l_i[4], O[4][8];
    #pragma unroll
    for (int i = 0; i < 4; i++) {
        m_i[i] = -1e30f; l_i[i] = 0.f;
        #pragma unroll
        for (int j = 0; j < 8; j++) O[i][j] = 0.f;
    }

    const float scale = 0.08838834764831845f;
    int nkb = qb + 1;

    for (int kb = 0; kb < nkb; kb++) {
        __syncthreads();

        #pragma unroll
        for (int it = 0; it < 8; it++) {
            int f4 = tid + it * 256;
            int r  = f4 >> 5;
            int d4 = (f4 & 31) * 4;
            int grow = base + (kb * 64 + r) * CDIM + d4;
            float4 kv = *(const float4*)(g_k + grow);
            Kt[(d4 + 0) * 64 + r] = kv.x;
            Kt[(d4 + 1) * 64 + r] = kv.y;
            Kt[(d4 + 2) * 64 + r] = kv.z;
            Kt[(d4 + 3) * 64 + r] = kv.w;
            *(float4*)&Vs[r * 128 + d4] = *(const float4*)(g_v + grow);
        }
        __syncthreads();

        float s[4][4];
        #pragma unroll
        for (int i = 0; i < 4; i++)
            #pragma unroll
            for (int j = 0; j < 4; j++) s[i][j] = 0.f;

        #pragma unroll 8
        for (int d = 0; d < 128; d++) {
            float4 qv = *(const float4*)(Qt + d * 64 + (ty << 2));
            float4 kv = *(const float4*)(Kt + d * 64 + (tx << 2));
            s[0][0] += qv.x * kv.x; s[0][1] += qv.x * kv.y; s[0][2] += qv.x * kv.z; s[0][3] += qv.x * kv.w;
            s[1][0] += qv.y * kv.x; s[1][1] += qv.y * kv.y; s[1][2] += qv.y * kv.z; s[1][3] += qv.y * kv.w;
            s[2][0] += qv.z * kv.x; s[2][1] += qv.z * kv.y; s[2][2] += qv.z * kv.z; s[2][3] += qv.z * kv.w;
            s[3][0] += qv.w * kv.x; s[3][1] += qv.w * kv.y; s[3][2] += qv.w * kv.z; s[3][3] += qv.w * kv.w;
        }

        #pragma unroll
        for (int i = 0; i < 4; i++) {
            int gq = qb * 64 + ty * 4 + i;
            float mx = -1e30f;
            #pragma unroll
            for (int j = 0; j < 4; j++) {
                int gk = kb * 64 + tx * 4 + j;
                float v = (gk <= gq) ? s[i][j] * scale : -1e9f;
                s[i][j] = v;
                mx = fmaxf(mx, v);
            }
            #pragma unroll
            for (int off = 8; off; off >>= 1)
                mx = fmaxf(mx, __shfl_xor_sync(0xffffffffu, mx, off));
            float mnew  = fmaxf(m_i[i], mx);
            float alpha = __expf(m_i[i] - mnew);
            float rs = 0.f;
            #pragma unroll
            for (int j = 0; j < 4; j++) {
                float p = __expf(s[i][j] - mnew);
                Ps[(ty * 4 + i) * 65 + tx * 4 + j] = p;
                rs += p;
            }
            #pragma unroll
            for (int off = 8; off; off >>= 1)
                rs += __shfl_xor_sync(0xffffffffu, rs, off);
            l_i[i] = l_i[i] * alpha + rs;
            m_i[i] = mnew;
            #pragma unroll
            for (int j = 0; j < 8; j++) O[i][j] *= alpha;
        }
        __syncthreads();

        #pragma unroll 4
        for (int kk = 0; kk < 64; kk++) {
            float p0 = Ps[(ty * 4 + 0) * 65 + kk];
            float p1 = Ps[(ty * 4 + 1) * 65 + kk];
            float p2 = Ps[(ty * 4 + 2) * 65 + kk];
            float p3 = Ps[(ty * 4 + 3) * 65 + kk];
            float4 va = *(const float4*)(Vs + kk * 128 + (tx << 3));
            float4 vb = *(const float4*)(Vs + kk * 128 + (tx << 3) + 4);
            O[0][0] += p0 * va.x; O[0][1] += p0 * va.y; O[0][2] += p0 * va.z; O[0][3] += p0 * va.w;
            O[0][4] += p0 * vb.x; O[0][5] += p0 * vb.y; O[0][6] += p0 * vb.z; O[0][7] += p0 * vb.w;
            O[1][0] += p1 * va.x; O[1][1] += p1 * va.y; O[1][2] += p1 * va.z; O[1][3] += p1 * va.w;
            O[1][4] += p1 * vb.x; O[1][5] += p1 * vb.y; O[1][6] += p1 * vb.z; O[1][7] += p1 * vb.w;
            O[2][0] += p2 * va.x; O[2][1] += p2 * va.y; O[2][2] += p2 * va.z; O[2][3] += p2 * va.w;
            O[2][4] += p2 * vb.x; O[2][5] += p2 * vb.y; O[2][6] += p2 * vb.z; O[2][7] += p2 * vb.w;
            O[3][0] += p3 * va.x; O[3][1] += p3 * va.y; O[3][2] += p3 * va.z; O[3][3] += p3 * va.w;
            O[3][4] += p3 * vb.x; O[3][5] += p3 * vb.y; O[3][6] += p3 * vb.z; O[3][7] += p3 * vb.w;
        }
    }

    #pragma unroll
    for (int i = 0; i < 4; i++) {
        float inv = 1.f / l_i[i];
        int r = qb * 64 + ty * 4 + i;
        float* po = g_att + base + r * CDIM + (tx << 3);
        float4 w0 = make_float4(O[i][0] * inv, O[i][1] * inv, O[i][2] * inv, O[i][3] * inv);
        float4 w1 = make_float4(O[i][4] * inv, O[i][5] * inv, O[i][6] * inv, O[i][7] * inv);
        *(float4*)(po)     = w0;
        *(float4*)(po + 4) = w1;
    }
}

// ===================== launch =====================
extern "C" void kernel_launch(void* const* d_in, const int* in_sizes, int n_in,
                              void* d_out, int out_size) {
    const float* x    = (const float*)d_in[0];
    const float* ln_g = (const float*)d_in[1];
    const float* ln_b = (const float*)d_in[2];
    const float* Wq   = (const float*)d_in[3];
    const float* bq   = (const float*)d_in[4];
    const float* Wk   = (const float*)d_in[5];
    const float* bk   = (const float*)d_in[6];
    const float* Wv   = (const float*)d_in[7];
    const float* bv   = (const float*)d_in[8];
    const float* Wo   = (const float*)d_in[9];
    const float* bo   = (const float*)d_in[10];
    float* out = (float*)d_out;

    float *nx, *qp, *kp, *vp, *ap;
    cudaGetSymbolAddress((void**)&nx, g_nx);
    cudaGetSymbolAddress((void**)&qp, g_q);
    cudaGetSymbolAddress((void**)&kp, g_k);
    cudaGetSymbolAddress((void**)&vp, g_v);
    cudaGetSymbolAddress((void**)&ap, g_att);

    cudaFuncSetAttribute(flash_kernel, cudaFuncAttributeMaxDynamicSharedMemorySize, FLASH_SMEM);

    ln_kernel<<<BTOT, 256>>>(x, ln_g, ln_b);

    dim3 gg(CDIM / 128, BTOT / 128);
    tgemm_kernel<0><<<gg, 256>>>(nx, Wq, bq, nullptr, qp, BTOT, CDIM, CDIM);
    tgemm_kernel<0><<<gg, 256>>>(nx, Wk, bk, nullptr, kp, BTOT, CDIM, CDIM);
    tgemm_kernel<0><<<gg, 256>>>(nx, Wv, bv, nullptr, vp, BTOT, CDIM, CDIM);

    rope_kernel<<<dim3(BTOT, 2), 256>>>();

    flash_kernel<<<dim3(TSEQ / 64, NHEAD, 4), 256, FLASH_SMEM>>>();

    tgemm_kernel<1><<<gg, 256>>>(ap, Wo, bo, x, out, BTOT, CDIM, CDIM);
}

// round 6
// speedup vs baseline: 3.6890x; 2.0656x over previous
#include <cuda_runtime.h>
#include <math.h>
#include <stdint.h>

#define BTOT 8192      // B*T rows
#define CDIM 2048      // channels
#define TSEQ 2048      // sequence length
#define NHEAD 16
#define HDIM 128

// -------- scratch (device globals; allocation-free) --------
__device__ float g_nx [BTOT * CDIM];
__device__ float g_q  [BTOT * CDIM];
__device__ float g_k  [BTOT * CDIM];
__device__ float g_v  [BTOT * CDIM];
__device__ float g_att[BTOT * CDIM];

__device__ __forceinline__ float to_tf32(float x) {
    uint32_t u;
    asm("cvt.rna.tf32.f32 %0, %1;" : "=r"(u) : "f"(x));
    return __uint_as_float(u);
}
__device__ __forceinline__ float4 tf32x4(float4 v) {
    return make_float4(to_tf32(v.x), to_tf32(v.y), to_tf32(v.z), to_tf32(v.w));
}

// ===================== LayerNorm =====================
__global__ __launch_bounds__(256) void ln_kernel(const float* __restrict__ x,
                                                 const float* __restrict__ gamma,
                                                 const float* __restrict__ beta) {
    int row = blockIdx.x;
    int tid = threadIdx.x;
    const float* px = x + row * CDIM;

    float4 a0 = *(const float4*)(px + tid * 4);
    float4 a1 = *(const float4*)(px + 1024 + tid * 4);

    float s = a0.x + a0.y + a0.z + a0.w + a1.x + a1.y + a1.z + a1.w;
    float q = a0.x*a0.x + a0.y*a0.y + a0.z*a0.z + a0.w*a0.w
            + a1.x*a1.x + a1.y*a1.y + a1.z*a1.z + a1.w*a1.w;

    #pragma unroll
    for (int off = 16; off; off >>= 1) {
        s += __shfl_xor_sync(0xffffffffu, s, off);
        q += __shfl_xor_sync(0xffffffffu, q, off);
    }
    __shared__ float sh[16];
    if ((tid & 31) == 0) { sh[tid >> 5] = s; sh[8 + (tid >> 5)] = q; }
    __syncthreads();
    float ts = 0.f, tq = 0.f;
    #pragma unroll
    for (int i = 0; i < 8; i++) { ts += sh[i]; tq += sh[8 + i]; }

    float mu   = ts * (1.f / 2048.f);
    float var  = tq * (1.f / 2048.f) - mu * mu;
    float rstd = rsqrtf(var + 1e-5f);

    float4 g0 = *(const float4*)(gamma + tid * 4);
    float4 g1 = *(const float4*)(gamma + 1024 + tid * 4);
    float4 b0 = *(const float4*)(beta + tid * 4);
    float4 b1 = *(const float4*)(beta + 1024 + tid * 4);

    float* po = g_nx + row * CDIM;
    float4 o0, o1;
    o0.x = (a0.x - mu) * rstd * g0.x + b0.x;
    o0.y = (a0.y - mu) * rstd * g0.y + b0.y;
    o0.z = (a0.z - mu) * rstd * g0.z + b0.z;
    o0.w = (a0.w - mu) * rstd * g0.w + b0.w;
    o1.x = (a1.x - mu) * rstd * g1.x + b1.x;
    o1.y = (a1.y - mu) * rstd * g1.y + b1.y;
    o1.z = (a1.z - mu) * rstd * g1.z + b1.z;
    o1.w = (a1.w - mu) * rstd * g1.w + b1.w;
    *(float4*)(po + tid * 4)        = o0;
    *(float4*)(po + 1024 + tid * 4) = o1;
}

// ===================== tf32 tensor-core GEMM =====================
template<int MODE>   // 0: +bias ; 1: +bias + residual
__global__ __launch_bounds__(256) void tgemm_kernel(const float* __restrict__ A,
                                                    const float* __restrict__ W,
                                                    const float* __restrict__ bias,
                                                    const float* __restrict__ R,
                                                    float* __restrict__ Y,
                                                    int M, int N, int K) {
    __shared__ float As[128][36];
    __shared__ float Bs[32][136];

    int tid  = threadIdx.x;
    int lane = tid & 31, warp = tid >> 5;
    int wm = warp >> 2;
    int wn = warp & 3;
    int bm = blockIdx.y * 128, bn = blockIdx.x * 128;

    int ldr = tid >> 3;
    int ldc = (tid & 7) * 4;

    const float* Ap = A + (size_t)(bm + ldr) * K + ldc;
    const float* Bp = W + (size_t)ldr * N + bn + ldc;

    float4 aR[4], bR[4];
    #pragma unroll
    for (int it = 0; it < 4; it++) {
        aR[it] = *(const float4*)(Ap + (size_t)(it * 32) * K);
        bR[it] = *(const float4*)(Bp + it * 32);
    }

    float c[4][4][4];
    #pragma unroll
    for (int mi = 0; mi < 4; mi++)
        #pragma unroll
        for (int ni = 0; ni < 4; ni++)
            #pragma unroll
            for (int r = 0; r < 4; r++) c[mi][ni][r] = 0.f;

    int mbase = wm * 64;
    int nbase = wn * 32;
    int lq = lane >> 2;
    int lr = lane & 3;

    for (int k0 = 0; k0 < K; k0 += 32) {
        #pragma unroll
        for (int it = 0; it < 4; it++) {
            *(float4*)&As[ldr + it * 32][ldc] = tf32x4(aR[it]);
            *(float4*)&Bs[ldr][ldc + it * 32] = tf32x4(bR[it]);
        }
        __syncthreads();

        if (k0 + 32 < K) {
            #pragma unroll
            for (int it = 0; it < 4; it++) {
                aR[it] = *(const float4*)(Ap + (size_t)(it * 32) * K + (k0 + 32));
                bR[it] = *(const float4*)(Bp + (size_t)(k0 + 32) * N + it * 32);
            }
        }

        #pragma unroll
        for (int kc = 0; kc < 4; kc++) {
            int kk = kc * 8;
            uint32_t a[4][4], b[4][2];
            #pragma unroll
            for (int mi = 0; mi < 4; mi++) {
                int r0 = mbase + mi * 16 + lq;
                int cc = kk + lr;
                a[mi][0] = __float_as_uint(As[r0    ][cc    ]);
                a[mi][1] = __float_as_uint(As[r0 + 8][cc    ]);
                a[mi][2] = __float_as_uint(As[r0    ][cc + 4]);
                a[mi][3] = __float_as_uint(As[r0 + 8][cc + 4]);
            }
            #pragma unroll
            for (int ni = 0; ni < 4; ni++) {
                int rr = kk + lr;
                int nc = nbase + ni * 8 + lq;
                b[ni][0] = __float_as_uint(Bs[rr    ][nc]);
                b[ni][1] = __float_as_uint(Bs[rr + 4][nc]);
            }
            #pragma unroll
            for (int mi = 0; mi < 4; mi++)
                #pragma unroll
                for (int ni = 0; ni < 4; ni++)
                    asm volatile(
                        "mma.sync.aligned.m16n8k8.row.col.f32.tf32.tf32.f32 "
                        "{%0,%1,%2,%3}, {%4,%5,%6,%7}, {%8,%9}, {%0,%1,%2,%3};"
                        : "+f"(c[mi][ni][0]), "+f"(c[mi][ni][1]),
                          "+f"(c[mi][ni][2]), "+f"(c[mi][ni][3])
                        : "r"(a[mi][0]), "r"(a[mi][1]), "r"(a[mi][2]), "r"(a[mi][3]),
                          "r"(b[ni][0]), "r"(b[ni][1]));
        }
        __syncthreads();
    }

    #pragma unroll
    for (int mi = 0; mi < 4; mi++) {
        int r0 = bm + mbase + mi * 16 + lq;
        #pragma unroll
        for (int ni = 0; ni < 4; ni++) {
            int cb = bn + nbase + ni * 8 + 2 * lr;
            float bx = bias[cb], by = bias[cb + 1];
            float2 v0 = make_float2(c[mi][ni][0] + bx, c[mi][ni][1] + by);
            float2 v1 = make_float2(c[mi][ni][2] + bx, c[mi][ni][3] + by);
            if (MODE == 1) {
                float2 r0v = *(const float2*)(R + (size_t)r0 * N + cb);
                float2 r1v = *(const float2*)(R + (size_t)(r0 + 8) * N + cb);
                v0.x += r0v.x; v0.y += r0v.y;
                v1.x += r1v.x; v1.y += r1v.y;
            }
            *(float2*)(Y + (size_t)r0 * N + cb)       = v0;
            *(float2*)(Y + (size_t)(r0 + 8) * N + cb) = v1;
        }
    }
}

// ===================== RoPE (in-place on g_q / g_k) =====================
__global__ __launch_bounds__(256) void rope_kernel() {
    int row = blockIdx.x;
    float* buf = (blockIdx.y == 0) ? g_q : g_k;
    int t = row & (TSEQ - 1);

    __shared__ float cs[64], sn[64];
    if (threadIdx.x < 64) {
        float inv = powf(10000.f, -(float)threadIdx.x / 64.f);
        float ang = (float)t * inv;
        cs[threadIdx.x] = cosf(ang);
        sn[threadIdx.x] = sinf(ang);
    }
    __syncthreads();

    float* p = buf + (size_t)row * CDIM;
    for (int idx = threadIdx.x; idx < NHEAD * 64; idx += 256) {
        int h = idx >> 6, f = idx & 63;
        float a = p[h * 128 + f];
        float b = p[h * 128 + 64 + f];
        p[h * 128 + f]      = a * cs[f] - b * sn[f];
        p[h * 128 + 64 + f] = b * cs[f] + a * sn[f];
    }
}

// ===================== Flash attention (tf32 tensor cores, causal) =====================
// grid: (T/128 [reversed], H, B); 256 threads = 8 warps; each warp owns 16 q-rows.
#define FLASH2_SMEM ((128*132 + 64*132 + 64*136 + 128*68) * 4)   // 171008 B

__global__ __launch_bounds__(256, 1) void flash_tc_kernel() {
    extern __shared__ float sm[];
    float* Qs = sm;                    // [128][132]
    float* Ks = Qs + 128 * 132;        // [64][132]
    float* Vs = Ks + 64 * 132;         // [64][136]
    float* Ps = Vs + 64 * 136;         // [128][68]

    int qb = gridDim.x - 1 - blockIdx.x;   // long blocks first
    int h = blockIdx.y, b = blockIdx.z;
    int tid = threadIdx.x, lane = tid & 31, warp = tid >> 5;
    int lq = lane >> 2, lr = lane & 3;

    size_t base = ((size_t)b * TSEQ) * CDIM + (size_t)h * HDIM;

    // Load Q tile (128 rows x 128 d), tf32-rounded
    #pragma unroll
    for (int it = 0; it < 16; it++) {
        int f4 = tid + it * 256;          // 0..4095
        int r  = f4 >> 5;                 // 0..127
        int c4 = (f4 & 31) * 4;
        float4 v = *(const float4*)(g_q + base + (size_t)(qb * 128 + r) * CDIM + c4);
        *(float4*)&Qs[r * 132 + c4] = tf32x4(v);
    }

    float m0 = -1e30f, m1 = -1e30f, l0 = 0.f, l1 = 0.f;
    float O[16][4];
    #pragma unroll
    for (int nt = 0; nt < 16; nt++)
        #pragma unroll
        for (int r = 0; r < 4; r++) O[nt][r] = 0.f;

    const float scale = 0.08838834764831845f;  // 1/sqrt(128)
    int arow = warp * 16 + lq;                  // local q row (lo); +8 = hi
    int prow0 = arow * 68, prow1 = (arow + 8) * 68;
    int grow0 = qb * 128 + arow;                // global q row (lo)

    int nkb = 2 * (qb + 1);
    for (int kb = 0; kb < nkb; kb++) {
        __syncthreads();   // prior PV done with Ks/Vs; Q visible (first iter)

        // Load K, V tiles (64 x 128 each), tf32-rounded
        #pragma unroll
        for (int it = 0; it < 8; it++) {
            int f4 = tid + it * 256;
            int r  = f4 >> 5;                 // 0..63
            int c4 = (f4 & 31) * 4;
            size_t g = base + (size_t)(kb * 64 + r) * CDIM + c4;
            *(float4*)&Ks[r * 132 + c4] = tf32x4(*(const float4*)(g_k + g));
            *(float4*)&Vs[r * 136 + c4] = tf32x4(*(const float4*)(g_v + g));
        }
        __syncthreads();

        // ---- S = Q K^T : warp computes 16x64 ----
        float s[8][4];
        #pragma unroll
        for (int nt = 0; nt < 8; nt++)
            #pragma unroll
            for (int r = 0; r < 4; r++) s[nt][r] = 0.f;

        #pragma unroll
        for (int kt = 0; kt < 16; kt++) {
            int kk = kt * 8;
            uint32_t a0 = __float_as_uint(Qs[arow * 132 + kk + lr]);
            uint32_t a1 = __float_as_uint(Qs[(arow + 8) * 132 + kk + lr]);
            uint32_t a2 = __float_as_uint(Qs[arow * 132 + kk + lr + 4]);
            uint32_t a3 = __float_as_uint(Qs[(arow + 8) * 132 + kk + lr + 4]);
            #pragma unroll
            for (int nt = 0; nt < 8; nt++) {
                int nc = nt * 8 + lq;
                uint32_t b0 = __float_as_uint(Ks[nc * 132 + kk + lr]);
                uint32_t b1 = __float_as_uint(Ks[nc * 132 + kk + lr + 4]);
                asm volatile(
                    "mma.sync.aligned.m16n8k8.row.col.f32.tf32.tf32.f32 "
                    "{%0,%1,%2,%3}, {%4,%5,%6,%7}, {%8,%9}, {%0,%1,%2,%3};"
                    : "+f"(s[nt][0]), "+f"(s[nt][1]), "+f"(s[nt][2]), "+f"(s[nt][3])
                    : "r"(a0), "r"(a1), "r"(a2), "r"(a3), "r"(b0), "r"(b1));
            }
        }

        // ---- scale + causal mask + online softmax (warp-local rows) ----
        // FIX (R5): mask needed whenever max key index exceeds the warp's MIN
        // query row (was: max row, which skipped masking on the diagonal block
        // for warps 3 and 7 -> future-key leakage, rel_err 8e-3).
        bool needmask = (kb * 64 + 63 > qb * 128 + warp * 16);
        float t0 = -1e30f, t1 = -1e30f;
        #pragma unroll
        for (int nt = 0; nt < 8; nt++) {
            if (needmask) {
                int c0 = kb * 64 + nt * 8 + 2 * lr;
                s[nt][0] = (c0     <= grow0)     ? s[nt][0] * scale : -1e30f;
                s[nt][1] = (c0 + 1 <= grow0)     ? s[nt][1] * scale : -1e30f;
                s[nt][2] = (c0     <= grow0 + 8) ? s[nt][2] * scale : -1e30f;
                s[nt][3] = (c0 + 1 <= grow0 + 8) ? s[nt][3] * scale : -1e30f;
            } else {
                s[nt][0] *= scale; s[nt][1] *= scale;
                s[nt][2] *= scale; s[nt][3] *= scale;
            }
            t0 = fmaxf(t0, fmaxf(s[nt][0], s[nt][1]));
            t1 = fmaxf(t1, fmaxf(s[nt][2], s[nt][3]));
        }
        t0 = fmaxf(t0, __shfl_xor_sync(0xffffffffu, t0, 1));
        t0 = fmaxf(t0, __shfl_xor_sync(0xffffffffu, t0, 2));
        t1 = fmaxf(t1, __shfl_xor_sync(0xffffffffu, t1, 1));
        t1 = fmaxf(t1, __shfl_xor_sync(0xffffffffu, t1, 2));

        float mn0 = fmaxf(m0, t0), mn1 = fmaxf(m1, t1);
        float al0 = __expf(m0 - mn0), al1 = __expf(m1 - mn1);
        float rs0 = 0.f, rs1 = 0.f;
        #pragma unroll
        for (int nt = 0; nt < 8; nt++) {
            float p00 = to_tf32(__expf(s[nt][0] - mn0));
            float p01 = to_tf32(__expf(s[nt][1] - mn0));
            float p10 = to_tf32(__expf(s[nt][2] - mn1));
            float p11 = to_tf32(__expf(s[nt][3] - mn1));
            rs0 += p00 + p01;
            rs1 += p10 + p11;
            *(float2*)&Ps[prow0 + nt * 8 + 2 * lr] = make_float2(p00, p01);
            *(float2*)&Ps[prow1 + nt * 8 + 2 * lr] = make_float2(p10, p11);
        }
        rs0 += __shfl_xor_sync(0xffffffffu, rs0, 1);
        rs0 += __shfl_xor_sync(0xffffffffu, rs0, 2);
        rs1 += __shfl_xor_sync(0xffffffffu, rs1, 1);
        rs1 += __shfl_xor_sync(0xffffffffu, rs1, 2);

        l0 = l0 * al0 + rs0;  l1 = l1 * al1 + rs1;
        m0 = mn0;             m1 = mn1;
        #pragma unroll
        for (int nt = 0; nt < 16; nt++) {
            O[nt][0] *= al0; O[nt][1] *= al0;
            O[nt][2] *= al1; O[nt][3] *= al1;
        }
        __syncwarp();   // Ps warp-private: order stores before cross-lane frag loads

        // ---- O += P V : warp computes 16x128 ----
        #pragma unroll
        for (int kt = 0; kt < 8; kt++) {
            int kk = kt * 8;
            uint32_t a0 = __float_as_uint(Ps[prow0 + kk + lr]);
            uint32_t a1 = __float_as_uint(Ps[prow1 + kk + lr]);
            uint32_t a2 = __float_as_uint(Ps[prow0 + kk + lr + 4]);
            uint32_t a3 = __float_as_uint(Ps[prow1 + kk + lr + 4]);
            #pragma unroll
            for (int nt = 0; nt < 16; nt++) {
                int nc = nt * 8 + lq;
                uint32_t b0 = __float_as_uint(Vs[(kk + lr) * 136 + nc]);
                uint32_t b1 = __float_as_uint(Vs[(kk + lr + 4) * 136 + nc]);
                asm volatile(
                    "mma.sync.aligned.m16n8k8.row.col.f32.tf32.tf32.f32 "
                    "{%0,%1,%2,%3}, {%4,%5,%6,%7}, {%8,%9}, {%0,%1,%2,%3};"
                    : "+f"(O[nt][0]), "+f"(O[nt][1]), "+f"(O[nt][2]), "+f"(O[nt][3])
                    : "r"(a0), "r"(a1), "r"(a2), "r"(a3), "r"(b0), "r"(b1));
            }
        }
    }

    // ---- epilogue: normalize + store ----
    float inv0 = 1.f / l0, inv1 = 1.f / l1;
    #pragma unroll
    for (int nt = 0; nt < 16; nt++) {
        int c = nt * 8 + 2 * lr;
        *(float2*)(g_att + base + (size_t)grow0 * CDIM + c) =
            make_float2(O[nt][0] * inv0, O[nt][1] * inv0);
        *(float2*)(g_att + base + (size_t)(grow0 + 8) * CDIM + c) =
            make_float2(O[nt][2] * inv1, O[nt][3] * inv1);
    }
}

// ===================== launch =====================
extern "C" void kernel_launch(void* const* d_in, const int* in_sizes, int n_in,
                              void* d_out, int out_size) {
    const float* x    = (const float*)d_in[0];
    const float* ln_g = (const float*)d_in[1];
    const float* ln_b = (const float*)d_in[2];
    const float* Wq   = (const float*)d_in[3];
    const float* bq   = (const float*)d_in[4];
    const float* Wk   = (const float*)d_in[5];
    const float* bk   = (const float*)d_in[6];
    const float* Wv   = (const float*)d_in[7];
    const float* bv   = (const float*)d_in[8];
    const float* Wo   = (const float*)d_in[9];
    const float* bo   = (const float*)d_in[10];
    float* out = (float*)d_out;

    float *nx, *qp, *kp, *vp, *ap;
    cudaGetSymbolAddress((void**)&nx, g_nx);
    cudaGetSymbolAddress((void**)&qp, g_q);
    cudaGetSymbolAddress((void**)&kp, g_k);
    cudaGetSymbolAddress((void**)&vp, g_v);
    cudaGetSymbolAddress((void**)&ap, g_att);

    cudaFuncSetAttribute(flash_tc_kernel, cudaFuncAttributeMaxDynamicSharedMemorySize, FLASH2_SMEM);

    ln_kernel<<<BTOT, 256>>>(x, ln_g, ln_b);

    dim3 gg(CDIM / 128, BTOT / 128);
    tgemm_kernel<0><<<gg, 256>>>(nx, Wq, bq, nullptr, qp, BTOT, CDIM, CDIM);
    tgemm_kernel<0><<<gg, 256>>>(nx, Wk, bk, nullptr, kp, BTOT, CDIM, CDIM);
    tgemm_kernel<0><<<gg, 256>>>(nx, Wv, bv, nullptr, vp, BTOT, CDIM, CDIM);

    rope_kernel<<<dim3(BTOT, 2), 256>>>();

    flash_tc_kernel<<<dim3(TSEQ / 128, NHEAD, 4), 256, FLASH2_SMEM>>>();

    tgemm_kernel<1><<<gg, 256>>>(ap, Wo, bo, x, out, BTOT, CDIM, CDIM);
}